// round 1
// baseline (speedup 1.0000x reference)
#include <cuda_runtime.h>

#define D_  48
#define H_  256
#define W_  256
#define DM_ 48
#define HM_ 128
#define WM_ 128
#define PH_ 4

#define NWARP (PH_ * D_ * H_ * W_)   // 12,582,912

__global__ void __launch_bounds__(256)
mvf_warp_kernel(const float* __restrict__ image,   // (D,H,W,2)
                const float* __restrict__ mvf,     // (PH,3,DM,HM,WM)
                float* __restrict__ out)           // full (5,D,H,W,2) base
{
    int idx = blockIdx.x * blockDim.x + threadIdx.x;
    if (idx >= NWARP) return;

    int x = idx & (W_ - 1);
    int y = (idx >> 8) & (H_ - 1);
    int t = idx >> 16;          // z + D_*p
    int z = t % D_;
    int p = t / D_;

    // ---- 2x upsample taps (jax.image.resize 'trilinear', edge-renormalized) ----
    float cy = 0.5f * (float)y - 0.25f;
    float fy = floorf(cy);
    int   jy0 = (int)fy;
    float wy1 = cy - fy;
    float wy0 = 1.0f - wy1;
    int   jy1 = jy0 + 1;
    if (jy0 < 0)        { jy0 = 0;        wy0 = 0.0f; wy1 = 1.0f; }
    if (jy1 > HM_ - 1)  { jy1 = HM_ - 1;  wy1 = 0.0f; wy0 = 1.0f; }

    float cx = 0.5f * (float)x - 0.25f;
    float fx = floorf(cx);
    int   jx0 = (int)fx;
    float wx1 = cx - fx;
    float wx0 = 1.0f - wx1;
    int   jx1 = jx0 + 1;
    if (jx0 < 0)        { jx0 = 0;        wx0 = 0.0f; wx1 = 1.0f; }
    if (jx1 > WM_ - 1)  { jx1 = WM_ - 1;  wx1 = 0.0f; wx0 = 1.0f; }

    const int plane = HM_ * WM_;
    int base = (p * 3 * DM_ + z) * plane;
    const int chstride = DM_ * plane;

    float m[3];
    #pragma unroll
    for (int ch = 0; ch < 3; ch++) {
        const float* s = mvf + base + ch * chstride;
        float v00 = s[jy0 * WM_ + jx0];
        float v01 = s[jy0 * WM_ + jx1];
        float v10 = s[jy1 * WM_ + jx0];
        float v11 = s[jy1 * WM_ + jx1];
        m[ch] = wy0 * (wx0 * v00 + wx1 * v01) + wy1 * (wx0 * v10 + wx1 * v11);
    }

    float zc = (float)z +        m[0];
    float yc = (float)y + 2.0f * m[1];
    float xc = (float)x + 2.0f * m[2];

    float zf = floorf(zc), yf = floorf(yc), xf = floorf(xc);
    int z0 = (int)zf, y0 = (int)yf, x0 = (int)xf;
    float wz = zc - zf, wy = yc - yf, wx = xc - xf;
    float wz0 = 1.0f - wz, wyA = 1.0f - wy, wxA = 1.0f - wx;

    float acc0 = 0.0f, acc1 = 0.0f;
    #pragma unroll
    for (int dz = 0; dz < 2; dz++) {
        int zi = z0 + dz;
        if ((unsigned)zi >= (unsigned)D_) continue;
        float wzc = dz ? wz : wz0;
        #pragma unroll
        for (int dy = 0; dy < 2; dy++) {
            int yi = y0 + dy;
            if ((unsigned)yi >= (unsigned)H_) continue;
            float wyc = wzc * (dy ? wy : wyA);
            int rowbase = (zi * H_ + yi) * W_;
            #pragma unroll
            for (int dx = 0; dx < 2; dx++) {
                int xi = x0 + dx;
                if ((unsigned)xi >= (unsigned)W_) continue;
                float w = wyc * (dx ? wx : wxA);
                float2 v = *reinterpret_cast<const float2*>(image + (size_t)(rowbase + xi) * 2);
                acc0 = fmaf(w, v.x, acc0);
                acc1 = fmaf(w, v.y, acc1);
            }
        }
    }

    // out[(1+p), z, y, x, :]
    size_t o = ((size_t)((1 + p) * D_ + z) * (H_ * W_) + (size_t)(y * W_ + x)) * 2;
    *reinterpret_cast<float2*>(out + o) = make_float2(acc0, acc1);
}

extern "C" void kernel_launch(void* const* d_in, const int* in_sizes, int n_in,
                              void* d_out, int out_size)
{
    const float* image = (const float*)d_in[0];   // (1,1,48,256,256,2) fp32
    const float* mvf   = (const float*)d_in[1];   // (1,4,3,48,128,128) fp32
    float* out = (float*)d_out;                   // (1,5,48,256,256,2) fp32

    // out[:,0] = image (25.2 MB D2D copy, graph-capturable)
    cudaMemcpyAsync(out, image, (size_t)D_ * H_ * W_ * 2 * sizeof(float),
                    cudaMemcpyDeviceToDevice, 0);

    const int threads = 256;
    const int blocks = (NWARP + threads - 1) / threads;
    mvf_warp_kernel<<<blocks, threads>>>(image, mvf, out);
}